// round 1
// baseline (speedup 1.0000x reference)
#include <cuda_runtime.h>

// EMA: y[0] = x[0]; y[t] = 0.3*x[t] + 0.7*y[t-1]
// Shape (B=64, T=4096, D=256), fp32.
//
// Strategy: 0.7^64 ~ 1.2e-10 << fp32 precision, so each T-chunk of 512 can be
// computed independently by warming up the recurrence from y=0 over a 64-step
// halo. Embarrassingly parallel streaming kernel, HBM-bound.

#define EMA_B 64
#define EMA_T 4096
#define EMA_D 256
#define EMA_CHUNK 512
#define EMA_HALO 64
#define EMA_S 0.3f
#define EMA_C 0.7f   // 1 - S

__global__ void __launch_bounds__(EMA_D, 8)
ema_kernel(const float* __restrict__ x, float* __restrict__ y) {
    const int d = threadIdx.x;                       // 0..255
    const int chunks_per_seq = EMA_T / EMA_CHUNK;    // 8
    const int chunk = blockIdx.x % chunks_per_seq;
    const int b     = blockIdx.x / chunks_per_seq;

    // Base pointers for this (b, d) lane; time stride = D floats.
    const float* __restrict__ xp = x + (b * EMA_T) * EMA_D + d;
    float*       __restrict__ yp = y + (b * EMA_T) * EMA_D + d;

    const int t0 = chunk * EMA_CHUNK;
    float acc;
    int t;

    if (chunk == 0) {
        // Exact start: y[0] = x[0]
        acc = xp[0];
        yp[0] = acc;
        t = 1;
    } else {
        // Halo warm-up from y=0 at t0-HALO; truncation error ~0.7^64 ~ 1e-10.
        acc = 0.0f;
        const int th = t0 - EMA_HALO;
#pragma unroll 8
        for (int k = 0; k < EMA_HALO; ++k) {
            acc = fmaf(EMA_C, acc, EMA_S * xp[(th + k) * EMA_D]);
        }
        t = t0;
    }

    const int tend = t0 + EMA_CHUNK;
#pragma unroll 8
    for (; t < tend; ++t) {
        acc = fmaf(EMA_C, acc, EMA_S * xp[t * EMA_D]);
        yp[t * EMA_D] = acc;
    }
}

extern "C" void kernel_launch(void* const* d_in, const int* in_sizes, int n_in,
                              void* d_out, int out_size) {
    const float* x = (const float*)d_in[0];
    float* y = (float*)d_out;
    const int grid = EMA_B * (EMA_T / EMA_CHUNK);   // 512 blocks
    ema_kernel<<<grid, EMA_D>>>(x, y);
}

// round 2
// speedup vs baseline: 1.1496x; 1.1496x over previous
#include <cuda_runtime.h>

// EMA: y[0] = x[0]; y[t] = 0.3*x[t] + 0.7*y[t-1]
// Shape (B=64, T=4096, D=256), fp32.
//
// Chunked-parallel scan: 0.7^32 ~ 1.1e-5 << 1e-3 tolerance, so each
// 256-step T-chunk is computed independently with a 32-step halo warm-up.
// float4-vectorized: each thread owns 4 channels (4 independent FMA chains),
// LDG.128/STG.128 for LSU efficiency and deep MLP.

#define EMA_B 64
#define EMA_T 4096
#define EMA_D 256
#define EMA_D4 (EMA_D / 4)        // 64 float4 lanes per timestep
#define EMA_CHUNK 256
#define EMA_NCHUNK (EMA_T / EMA_CHUNK)   // 16
#define EMA_HALO 32
#define EMA_S 0.3f
#define EMA_C 0.7f

__global__ void __launch_bounds__(EMA_D4)
ema_kernel(const float4* __restrict__ x, float4* __restrict__ y) {
    const int lane  = threadIdx.x;                // 0..63: channel quad
    const int chunk = blockIdx.x % EMA_NCHUNK;
    const int b     = blockIdx.x / EMA_NCHUNK;

    const float4* __restrict__ xp = x + (size_t)b * EMA_T * EMA_D4 + lane;
    float4*       __restrict__ yp = y + (size_t)b * EMA_T * EMA_D4 + lane;

    const int t0 = chunk * EMA_CHUNK;

    float a0, a1, a2, a3;
    if (chunk == 0) {
        // Seed acc = x[0] so the first main-loop step yields
        // y[0] = 0.3*x0 + 0.7*x0 = x0 (exact to 1 ulp).
        float4 v = xp[0];
        a0 = v.x; a1 = v.y; a2 = v.z; a3 = v.w;
    } else {
        // Halo warm-up from zero; truncation ~0.7^32 ~ 1.1e-5.
        a0 = a1 = a2 = a3 = 0.0f;
        const int th = t0 - EMA_HALO;
#pragma unroll 8
        for (int k = 0; k < EMA_HALO; ++k) {
            float4 v = xp[(th + k) * EMA_D4];
            a0 = fmaf(EMA_C, a0, EMA_S * v.x);
            a1 = fmaf(EMA_C, a1, EMA_S * v.y);
            a2 = fmaf(EMA_C, a2, EMA_S * v.z);
            a3 = fmaf(EMA_C, a3, EMA_S * v.w);
        }
    }

#pragma unroll 8
    for (int t = t0; t < t0 + EMA_CHUNK; ++t) {
        float4 v = xp[t * EMA_D4];
        a0 = fmaf(EMA_C, a0, EMA_S * v.x);
        a1 = fmaf(EMA_C, a1, EMA_S * v.y);
        a2 = fmaf(EMA_C, a2, EMA_S * v.z);
        a3 = fmaf(EMA_C, a3, EMA_S * v.w);
        float4 o;
        o.x = a0; o.y = a1; o.z = a2; o.w = a3;
        yp[t * EMA_D4] = o;
    }
}

extern "C" void kernel_launch(void* const* d_in, const int* in_sizes, int n_in,
                              void* d_out, int out_size) {
    const float4* x = (const float4*)d_in[0];
    float4* y = (float4*)d_out;
    const int grid = EMA_B * EMA_NCHUNK;   // 1024 blocks of 64 threads
    ema_kernel<<<grid, EMA_D4>>>(x, y);
}

// round 3
// speedup vs baseline: 1.2249x; 1.0655x over previous
#include <cuda_runtime.h>

// EMA: y[0] = x[0]; y[t] = 0.3*x[t] + 0.7*y[t-1]
// Shape (B=64, T=4096, D=256), fp32.
//
// Chunked-parallel scan: 0.7^24 ~ 1.9e-4, empirical error factor ~0.06 ->
// rel_err ~1e-5 << 1e-3 tolerance. Each 128-step T-chunk computed
// independently with a 24-step halo warm-up. float4 lanes, streaming stores.

#define EMA_B 64
#define EMA_T 4096
#define EMA_D 256
#define EMA_D4 (EMA_D / 4)               // 64 float4 lanes per timestep
#define EMA_CHUNK 128
#define EMA_NCHUNK (EMA_T / EMA_CHUNK)   // 32
#define EMA_HALO 24
#define EMA_S 0.3f
#define EMA_C 0.7f

__global__ void __launch_bounds__(EMA_D4)
ema_kernel(const float4* __restrict__ x, float4* __restrict__ y) {
    const int lane  = threadIdx.x;                 // 0..63: channel quad
    const int chunk = blockIdx.x % EMA_NCHUNK;     // adjacent blocks = adjacent
    const int b     = blockIdx.x / EMA_NCHUNK;     // chunks -> halo L2 reuse

    const float4* __restrict__ xp = x + (size_t)b * EMA_T * EMA_D4 + lane;
    float4*       __restrict__ yp = y + (size_t)b * EMA_T * EMA_D4 + lane;

    const int t0 = chunk * EMA_CHUNK;

    float a0, a1, a2, a3;
    if (chunk == 0) {
        // Seed acc = x[0]: first main-loop step gives y[0] = 0.3x0+0.7x0 = x0.
        float4 v = xp[0];
        a0 = v.x; a1 = v.y; a2 = v.z; a3 = v.w;
    } else {
        // Halo warm-up from zero.
        a0 = a1 = a2 = a3 = 0.0f;
        const int th = t0 - EMA_HALO;
#pragma unroll 8
        for (int k = 0; k < EMA_HALO; ++k) {
            float4 v = xp[(th + k) * EMA_D4];
            a0 = fmaf(EMA_C, a0, EMA_S * v.x);
            a1 = fmaf(EMA_C, a1, EMA_S * v.y);
            a2 = fmaf(EMA_C, a2, EMA_S * v.z);
            a3 = fmaf(EMA_C, a3, EMA_S * v.w);
        }
    }

    // Main loop, software-pipelined one load ahead so the LDG for t+1 issues
    // before the FMA chain for t retires.
    float4 v = xp[t0 * EMA_D4];
#pragma unroll 8
    for (int t = t0; t < t0 + EMA_CHUNK - 1; ++t) {
        float4 vn = xp[(t + 1) * EMA_D4];
        a0 = fmaf(EMA_C, a0, EMA_S * v.x);
        a1 = fmaf(EMA_C, a1, EMA_S * v.y);
        a2 = fmaf(EMA_C, a2, EMA_S * v.z);
        a3 = fmaf(EMA_C, a3, EMA_S * v.w);
        __stcs(&yp[t * EMA_D4], make_float4(a0, a1, a2, a3));
        v = vn;
    }
    {
        const int t = t0 + EMA_CHUNK - 1;
        a0 = fmaf(EMA_C, a0, EMA_S * v.x);
        a1 = fmaf(EMA_C, a1, EMA_S * v.y);
        a2 = fmaf(EMA_C, a2, EMA_S * v.z);
        a3 = fmaf(EMA_C, a3, EMA_S * v.w);
        __stcs(&yp[t * EMA_D4], make_float4(a0, a1, a2, a3));
    }
}

extern "C" void kernel_launch(void* const* d_in, const int* in_sizes, int n_in,
                              void* d_out, int out_size) {
    const float4* x = (const float4*)d_in[0];
    float4* y = (float4*)d_out;
    const int grid = EMA_B * EMA_NCHUNK;   // 2048 blocks of 64 threads
    ema_kernel<<<grid, EMA_D4>>>(x, y);
}